// round 9
// baseline (speedup 1.0000x reference)
#include <cuda_runtime.h>

#define N_NODES 50000
#define N_EDGES 800000
#define F 64
#define NCLS 10

#define SCAN_CHUNK 512
#define SCAN_BLOCKS ((N_NODES + SCAN_CHUNK - 1) / SCAN_CHUNK)   // 98
#define NODE_BLOCKS ((N_NODES + 255) / 256)                      // 196

// Scratch (__device__ globals; accessed directly as symbols).
__device__ float g_h[N_NODES * F];
__device__ float g_x[N_NODES * F];
__device__ int   g_deg[N_NODES];
__device__ int   g_offs[N_NODES + 1];
__device__ int   g_cursor[N_NODES];
__device__ int   g_csr[N_EDGES];
__device__ int   g_agg_sum[SCAN_BLOCKS];
__device__ int   g_incl[SCAN_BLOCKS];
__device__ int   g_state[SCAN_BLOCKS];   // 0=invalid, 1=aggregate, 2=prefix
__device__ int   g_is64;

// ---------------------------------------------------------------------------
// init: zero degree counters + (last block) dtype detect + scan-state reset
// ---------------------------------------------------------------------------
__global__ void init_kernel(const int* __restrict__ edges_raw) {
    if (blockIdx.x < NODE_BLOCKS) {
        int i = blockIdx.x * 256 + threadIdx.x;
        if (i < N_NODES) g_deg[i] = 0;
    } else {
        __shared__ int any_nonzero;
        if (threadIdx.x == 0) any_nonzero = 0;
        __syncthreads();
        for (int i = threadIdx.x; i < SCAN_BLOCKS; i += 256) g_state[i] = 0;
        int nz = 0;
        for (int i = threadIdx.x; i < 2048; i += 256)
            if (edges_raw[2 * i + 1] != 0) nz = 1;
        if (nz) any_nonzero = 1;
        __syncthreads();
        if (threadIdx.x == 0) g_is64 = (any_nonzero == 0) ? 1 : 0;
    }
}

__device__ __forceinline__ int load_id(const int* __restrict__ raw, int is64, int idx) {
    return is64 ? raw[2 * idx] : raw[idx];
}

__global__ void hist_kernel(const int* __restrict__ edges_raw) {
    int e = blockIdx.x * blockDim.x + threadIdx.x;
    if (e < N_EDGES) {
        int d = load_id(edges_raw, g_is64, N_EDGES + e);
        atomicAdd(&g_deg[d], 1);
    }
}

// ---------------------------------------------------------------------------
// Single-pass exclusive scan (decoupled lookback). 98 blocks, all co-resident
// on 148 SMs -> no deadlock. Writes g_offs + g_cursor.
// ---------------------------------------------------------------------------
__global__ void scan_onepass_kernel() {
    __shared__ int warp_sums[SCAN_CHUNK / 32];   // 16
    __shared__ int s_excl;
    int tid  = threadIdx.x;
    int b    = blockIdx.x;
    int gid  = b * SCAN_CHUNK + tid;
    int lane = tid & 31;
    int wid  = tid >> 5;

    int v = (gid < N_NODES) ? g_deg[gid] : 0;
    int x = v;
#pragma unroll
    for (int off = 1; off < 32; off <<= 1) {
        int y = __shfl_up_sync(0xFFFFFFFFu, x, off);
        if (lane >= off) x += y;
    }
    if (lane == 31) warp_sums[wid] = x;
    __syncthreads();
    if (wid == 0) {
        int s = (lane < 16) ? warp_sums[lane] : 0;
#pragma unroll
        for (int off = 1; off < 16; off <<= 1) {
            int y = __shfl_up_sync(0xFFFFFFFFu, s, off);
            if (lane >= off) s += y;
        }
        if (lane < 16) warp_sums[lane] = s;
    }
    __syncthreads();
    int base  = (wid > 0) ? warp_sums[wid - 1] : 0;
    int incl  = base + x;             // inclusive within block
    int total = warp_sums[15];        // block total

    if (tid == 0) {
        if (b == 0) {
            g_incl[0] = total;
            __threadfence();
            atomicExch(&g_state[0], 2);
            s_excl = 0;
        } else {
            g_agg_sum[b] = total;
            __threadfence();
            atomicExch(&g_state[b], 1);
            int excl = 0;
            int p = b - 1;
            while (true) {
                int st;
                do { st = atomicAdd(&g_state[p], 0); } while (st == 0);
                if (st == 2) { excl += atomicAdd(&g_incl[p], 0); break; }
                excl += atomicAdd(&g_agg_sum[p], 0);
                p--;
            }
            g_incl[b] = excl + total;
            __threadfence();
            atomicExch(&g_state[b], 2);
            s_excl = excl;
        }
    }
    __syncthreads();
    int o = s_excl + incl - v;
    if (gid < N_NODES) { g_offs[gid] = o; g_cursor[gid] = o; }
    if (b == SCAN_BLOCKS - 1 && tid == SCAN_CHUNK - 1) g_offs[N_NODES] = s_excl + incl;
}

__global__ void csr_scatter_kernel(const int* __restrict__ edges_raw) {
    int e = blockIdx.x * blockDim.x + threadIdx.x;
    if (e >= N_EDGES) return;
    int is64 = g_is64;
    int s = load_id(edges_raw, is64, e);
    int d = load_id(edges_raw, is64, N_EDGES + e);
    int pos = atomicAdd(&g_cursor[d], 1);
    g_csr[pos] = s;
}

// ---------------------------------------------------------------------------
// Aggregation (gather): g_h[n] = x[n] + sum_{s in N_in(n)} x[s]
// 16 threads per node, float4 per thread, neighbor loop unrolled x4.
// ---------------------------------------------------------------------------
__global__ void agg_kernel(const float* __restrict__ feat, int first) {
    const float* __restrict__ x = first ? feat : (const float*)g_x;
    int tid  = threadIdx.x;
    int node = blockIdx.x * 16 + (tid >> 4);
    int t    = tid & 15;
    if (node >= N_NODES) return;

    float4 acc = *(const float4*)(x + (size_t)node * F + t * 4);
    int jb = g_offs[node];
    int je = g_offs[node + 1];
    int j  = jb;
    for (; j + 3 < je; j += 4) {
        int s0 = g_csr[j], s1 = g_csr[j + 1], s2 = g_csr[j + 2], s3 = g_csr[j + 3];
        float4 v0 = *(const float4*)(x + (size_t)s0 * F + t * 4);
        float4 v1 = *(const float4*)(x + (size_t)s1 * F + t * 4);
        float4 v2 = *(const float4*)(x + (size_t)s2 * F + t * 4);
        float4 v3 = *(const float4*)(x + (size_t)s3 * F + t * 4);
        acc.x += v0.x; acc.y += v0.y; acc.z += v0.z; acc.w += v0.w;
        acc.x += v1.x; acc.y += v1.y; acc.z += v1.z; acc.w += v1.w;
        acc.x += v2.x; acc.y += v2.y; acc.z += v2.z; acc.w += v2.w;
        acc.x += v3.x; acc.y += v3.y; acc.z += v3.z; acc.w += v3.w;
    }
    for (; j < je; j++) {
        int s = g_csr[j];
        float4 v = *(const float4*)(x + (size_t)s * F + t * 4);
        acc.x += v.x; acc.y += v.y; acc.z += v.z; acc.w += v.w;
    }
    *(float4*)(g_h + (size_t)node * F + t * 4) = acc;
}

// ---------------------------------------------------------------------------
// MLP: g_x = relu( relu(g_h @ W1 + b1) @ W2 + b2 )
// 128-row tile, 512 threads as 16x32, 4x4 microtile. smem = 48KB exactly.
// If last != 0: instead of writing g_x, apply the final Linear (64->10)
// in-block and write d_out directly (saves a kernel + 25.6MB round trip).
// ---------------------------------------------------------------------------
__global__ __launch_bounds__(512) void mlp_kernel(
        const float* __restrict__ W1, const float* __restrict__ b1,
        const float* __restrict__ W2, const float* __restrict__ b2,
        const float* __restrict__ Wl, const float* __restrict__ bl,
        float* __restrict__ out, int last) {
    __shared__ float Hs[128][64];
    __shared__ float Ws[64][64];

    int tid = threadIdx.x;
    int tx = tid & 15;          // col group (4 cols)
    int ty = tid >> 4;          // row group (4 rows), 0..31
    int row0 = blockIdx.x * 128;

    for (int i = tid; i < 128 * 16; i += 512) {
        int r = i >> 4;
        int c = (i & 15) << 2;
        float4 v = make_float4(0.f, 0.f, 0.f, 0.f);
        if (row0 + r < N_NODES) v = *(const float4*)(g_h + (size_t)(row0 + r) * F + c);
        *(float4*)&Hs[r][c] = v;
    }
    for (int i = tid; i < 1024; i += 512)
        ((float4*)&Ws[0][0])[i] = ((const float4*)W1)[i];
    float4 bias = *(const float4*)&b1[tx * 4];
    __syncthreads();

    float acc[4][4];
#pragma unroll
    for (int i = 0; i < 4; i++) {
        acc[i][0] = bias.x; acc[i][1] = bias.y; acc[i][2] = bias.z; acc[i][3] = bias.w;
    }

    // Stage 1: T = relu(H @ W1 + b1)
#pragma unroll 8
    for (int k = 0; k < 64; k++) {
        float a0 = Hs[ty * 4 + 0][k];
        float a1 = Hs[ty * 4 + 1][k];
        float a2 = Hs[ty * 4 + 2][k];
        float a3 = Hs[ty * 4 + 3][k];
        float4 b = *(float4*)&Ws[k][tx * 4];
        acc[0][0] += a0 * b.x; acc[0][1] += a0 * b.y; acc[0][2] += a0 * b.z; acc[0][3] += a0 * b.w;
        acc[1][0] += a1 * b.x; acc[1][1] += a1 * b.y; acc[1][2] += a1 * b.z; acc[1][3] += a1 * b.w;
        acc[2][0] += a2 * b.x; acc[2][1] += a2 * b.y; acc[2][2] += a2 * b.z; acc[2][3] += a2 * b.w;
        acc[3][0] += a3 * b.x; acc[3][1] += a3 * b.y; acc[3][2] += a3 * b.z; acc[3][3] += a3 * b.w;
    }
    __syncthreads();

    // T = relu(acc) into Hs; load W2
#pragma unroll
    for (int i = 0; i < 4; i++)
#pragma unroll
        for (int j = 0; j < 4; j++)
            Hs[ty * 4 + i][tx * 4 + j] = fmaxf(acc[i][j], 0.f);
    for (int i = tid; i < 1024; i += 512)
        ((float4*)&Ws[0][0])[i] = ((const float4*)W2)[i];
    bias = *(const float4*)&b2[tx * 4];
    __syncthreads();

#pragma unroll
    for (int i = 0; i < 4; i++) {
        acc[i][0] = bias.x; acc[i][1] = bias.y; acc[i][2] = bias.z; acc[i][3] = bias.w;
    }

    // Stage 2: O = relu(T @ W2 + b2)
#pragma unroll 8
    for (int k = 0; k < 64; k++) {
        float a0 = Hs[ty * 4 + 0][k];
        float a1 = Hs[ty * 4 + 1][k];
        float a2 = Hs[ty * 4 + 2][k];
        float a3 = Hs[ty * 4 + 3][k];
        float4 b = *(float4*)&Ws[k][tx * 4];
        acc[0][0] += a0 * b.x; acc[0][1] += a0 * b.y; acc[0][2] += a0 * b.z; acc[0][3] += a0 * b.w;
        acc[1][0] += a1 * b.x; acc[1][1] += a1 * b.y; acc[1][2] += a1 * b.z; acc[1][3] += a1 * b.w;
        acc[2][0] += a2 * b.x; acc[2][1] += a2 * b.y; acc[2][2] += a2 * b.z; acc[2][3] += a2 * b.w;
        acc[3][0] += a3 * b.x; acc[3][1] += a3 * b.y; acc[3][2] += a3 * b.z; acc[3][3] += a3 * b.w;
    }

    if (!last) {
#pragma unroll
        for (int i = 0; i < 4; i++) {
            int r = row0 + ty * 4 + i;
            if (r < N_NODES) {
                float4 o;
                o.x = fmaxf(acc[i][0], 0.f); o.y = fmaxf(acc[i][1], 0.f);
                o.z = fmaxf(acc[i][2], 0.f); o.w = fmaxf(acc[i][3], 0.f);
                *(float4*)(g_x + (size_t)r * F + tx * 4) = o;
            }
        }
    } else {
        // Fused final Linear: out = relu(O) @ W_lin + b_lin
        __syncthreads();   // stage-2 Hs reads done in all warps
#pragma unroll
        for (int i = 0; i < 4; i++)
#pragma unroll
            for (int j = 0; j < 4; j++)
                Hs[ty * 4 + i][tx * 4 + j] = fmaxf(acc[i][j], 0.f);
        float* Wsf = &Ws[0][0];
        for (int i = tid; i < 64 * NCLS + NCLS; i += 512)
            Wsf[i] = (i < 64 * NCLS) ? Wl[i] : bl[i - 64 * NCLS];
        __syncthreads();

        int c     = tid & 15;          // class column (c<10 active)
        int rbase = tid >> 4;          // 0..31, rows rbase + 32*i
        if (c < NCLS) {
            float acc2[4];
#pragma unroll
            for (int i = 0; i < 4; i++) acc2[i] = Wsf[64 * NCLS + c];
            for (int k = 0; k < 64; k++) {
                float w = Wsf[k * NCLS + c];
#pragma unroll
                for (int i = 0; i < 4; i++) acc2[i] += Hs[rbase + 32 * i][k] * w;
            }
#pragma unroll
            for (int i = 0; i < 4; i++) {
                int r = row0 + rbase + 32 * i;
                if (r < N_NODES) out[(size_t)r * NCLS + c] = acc2[i];
            }
        }
    }
}

// ---------------------------------------------------------------------------
// Launch: kernel launches ONLY. 10 launches total.
// ---------------------------------------------------------------------------
extern "C" void kernel_launch(void* const* d_in, const int* in_sizes, int n_in,
                              void* d_out, int out_size) {
    const float* feat      = (const float*)d_in[0];
    const int*   edges_raw = (const int*)d_in[1];

    const float* W1[3] = { (const float*)d_in[2],  (const float*)d_in[6],  (const float*)d_in[10] };
    const float* b1[3] = { (const float*)d_in[3],  (const float*)d_in[7],  (const float*)d_in[11] };
    const float* W2[3] = { (const float*)d_in[4],  (const float*)d_in[8],  (const float*)d_in[12] };
    const float* b2[3] = { (const float*)d_in[5],  (const float*)d_in[9],  (const float*)d_in[13] };
    const float* Wl = (const float*)d_in[14];
    const float* bl = (const float*)d_in[15];
    float* out = (float*)d_out;

    dim3 edge_grid((N_EDGES + 255) / 256);
    dim3 agg_grid((N_NODES + 15) / 16);
    dim3 mlp_grid((N_NODES + 127) / 128);

    init_kernel<<<NODE_BLOCKS + 1, 256>>>(edges_raw);
    hist_kernel<<<edge_grid, 256>>>(edges_raw);
    scan_onepass_kernel<<<SCAN_BLOCKS, SCAN_CHUNK>>>();
    csr_scatter_kernel<<<edge_grid, 256>>>(edges_raw);

    for (int l = 0; l < 3; l++) {
        agg_kernel<<<agg_grid, 256>>>(feat, l == 0 ? 1 : 0);
        mlp_kernel<<<mlp_grid, 512>>>(W1[l], b1[l], W2[l], b2[l],
                                      Wl, bl, out, l == 2 ? 1 : 0);
    }
}

// round 10
// speedup vs baseline: 1.0309x; 1.0309x over previous
#include <cuda_runtime.h>

#define N_NODES 50000
#define N_EDGES 800000
#define F 64
#define NCLS 10

#define SCAN_CHUNK 512
#define SCAN_BLOCKS ((N_NODES + SCAN_CHUNK - 1) / SCAN_CHUNK)   // 98
#define NODE_BLOCKS ((N_NODES + 255) / 256)                      // 196

// Scratch (__device__ globals; accessed directly as symbols).
__device__ float g_h[N_NODES * F];
__device__ float g_x[N_NODES * F];
__device__ int   g_deg[N_NODES];
__device__ int   g_offs[N_NODES + 1];
__device__ int   g_cursor[N_NODES];
__device__ int   g_csr[N_EDGES];
__device__ int   g_blocksum[SCAN_BLOCKS];
__device__ int   g_is64;

// ---------------------------------------------------------------------------
// init: zero degree counters + dtype detect (last block)
// ---------------------------------------------------------------------------
__global__ void init_kernel(const int* __restrict__ edges_raw) {
    if (blockIdx.x < NODE_BLOCKS) {
        int i = blockIdx.x * 256 + threadIdx.x;
        if (i < N_NODES) g_deg[i] = 0;
    } else {
        __shared__ int any_nonzero;
        if (threadIdx.x == 0) any_nonzero = 0;
        __syncthreads();
        int nz = 0;
        for (int i = threadIdx.x; i < 2048; i += 256)
            if (edges_raw[2 * i + 1] != 0) nz = 1;
        if (nz) any_nonzero = 1;
        __syncthreads();
        if (threadIdx.x == 0) g_is64 = (any_nonzero == 0) ? 1 : 0;
    }
}

// ---------------------------------------------------------------------------
// Vectorized edge-id loaders: 4 contiguous ids per call (one/two LDG.128).
// base_elt = 0 for src row, N_EDGES for dst row. e0 multiple of 4.
// ---------------------------------------------------------------------------
__device__ __forceinline__ void load_ids4(const int* __restrict__ raw, int is64,
                                          int base_elt, int e0, int* ids) {
    if (is64) {
        // int64 layout: element i at 8-byte offset. int4 = 2 int64s.
        const int4* p = (const int4*)raw + ((size_t)(base_elt + e0) >> 1);
        int4 a = p[0], b = p[1];
        ids[0] = a.x; ids[1] = a.z; ids[2] = b.x; ids[3] = b.z;
    } else {
        int4 a = *((const int4*)raw + ((size_t)(base_elt + e0) >> 2));
        ids[0] = a.x; ids[1] = a.y; ids[2] = a.z; ids[3] = a.w;
    }
}

// hist: 4 edges per thread -> 4 independent atomics in flight
__global__ void hist_kernel(const int* __restrict__ edges_raw) {
    int e0 = (blockIdx.x * blockDim.x + threadIdx.x) * 4;
    if (e0 >= N_EDGES) return;
    int d[4];
    load_ids4(edges_raw, g_is64, N_EDGES, e0, d);
#pragma unroll
    for (int i = 0; i < 4; i++) atomicAdd(&g_deg[d[i]], 1);
}

// Scan step 1: per-block exclusive scan via warp shuffles.
__global__ void scan_local_kernel() {
    __shared__ int warp_sums[SCAN_CHUNK / 32];
    int tid  = threadIdx.x;
    int gid  = blockIdx.x * SCAN_CHUNK + tid;
    int lane = tid & 31;
    int wid  = tid >> 5;

    int v = (gid < N_NODES) ? g_deg[gid] : 0;
    int x = v;
#pragma unroll
    for (int off = 1; off < 32; off <<= 1) {
        int y = __shfl_up_sync(0xFFFFFFFFu, x, off);
        if (lane >= off) x += y;
    }
    if (lane == 31) warp_sums[wid] = x;
    __syncthreads();
    if (wid == 0) {
        int s = (lane < SCAN_CHUNK / 32) ? warp_sums[lane] : 0;
#pragma unroll
        for (int off = 1; off < SCAN_CHUNK / 32; off <<= 1) {
            int y = __shfl_up_sync(0xFFFFFFFFu, s, off);
            if (lane >= off) s += y;
        }
        if (lane < SCAN_CHUNK / 32) warp_sums[lane] = s;
    }
    __syncthreads();
    int base = (wid > 0) ? warp_sums[wid - 1] : 0;
    int incl = base + x;
    if (gid < N_NODES) g_offs[gid] = incl - v;
    if (tid == SCAN_CHUNK - 1) g_blocksum[blockIdx.x] = incl;
}

// Scan step 2: scan the 98 block sums.
__global__ void scan_spine_kernel() {
    __shared__ int ws[4];
    int tid  = threadIdx.x;
    int lane = tid & 31;
    int wid  = tid >> 5;
    int v = (tid < SCAN_BLOCKS) ? g_blocksum[tid] : 0;
    int x = v;
#pragma unroll
    for (int off = 1; off < 32; off <<= 1) {
        int y = __shfl_up_sync(0xFFFFFFFFu, x, off);
        if (lane >= off) x += y;
    }
    if (lane == 31) ws[wid] = x;
    __syncthreads();
    if (tid == 0) {
        int r = 0;
#pragma unroll
        for (int i = 0; i < 4; i++) { int t = ws[i]; ws[i] = r; r += t; }
    }
    __syncthreads();
    int excl = ws[wid] + x - v;
    if (tid < SCAN_BLOCKS) g_blocksum[tid] = excl;
    if (tid == SCAN_BLOCKS - 1) g_offs[N_NODES] = excl + v;
}

// Scan step 3: add spine; materialize offs + cursor.
__global__ void scan_add_kernel() {
    int gid = blockIdx.x * SCAN_CHUNK + threadIdx.x;
    if (gid < N_NODES) {
        int o = g_offs[gid] + g_blocksum[blockIdx.x];
        g_offs[gid]   = o;
        g_cursor[gid] = o;
    }
}

// scatter: 4 edges per thread -> 4 independent ATOMG+STG chains
__global__ void csr_scatter_kernel(const int* __restrict__ edges_raw) {
    int e0 = (blockIdx.x * blockDim.x + threadIdx.x) * 4;
    if (e0 >= N_EDGES) return;
    int is64 = g_is64;
    int s[4], d[4];
    load_ids4(edges_raw, is64, 0,       e0, s);
    load_ids4(edges_raw, is64, N_EDGES, e0, d);
    int pos[4];
#pragma unroll
    for (int i = 0; i < 4; i++) pos[i] = atomicAdd(&g_cursor[d[i]], 1);
#pragma unroll
    for (int i = 0; i < 4; i++) g_csr[pos[i]] = s[i];
}

// ---------------------------------------------------------------------------
// Aggregation (gather): g_h[n] = x[n] + sum_{s in N_in(n)} x[s]
// 16 threads per node, float4 per thread, neighbor loop unrolled x4.
// ---------------------------------------------------------------------------
__global__ void agg_kernel(const float* __restrict__ feat, int first) {
    const float* __restrict__ x = first ? feat : (const float*)g_x;
    int tid  = threadIdx.x;
    int node = blockIdx.x * 16 + (tid >> 4);
    int t    = tid & 15;
    if (node >= N_NODES) return;

    float4 acc = *(const float4*)(x + (size_t)node * F + t * 4);
    int jb = g_offs[node];
    int je = g_offs[node + 1];
    int j  = jb;
    for (; j + 3 < je; j += 4) {
        int s0 = g_csr[j], s1 = g_csr[j + 1], s2 = g_csr[j + 2], s3 = g_csr[j + 3];
        float4 v0 = *(const float4*)(x + (size_t)s0 * F + t * 4);
        float4 v1 = *(const float4*)(x + (size_t)s1 * F + t * 4);
        float4 v2 = *(const float4*)(x + (size_t)s2 * F + t * 4);
        float4 v3 = *(const float4*)(x + (size_t)s3 * F + t * 4);
        acc.x += v0.x; acc.y += v0.y; acc.z += v0.z; acc.w += v0.w;
        acc.x += v1.x; acc.y += v1.y; acc.z += v1.z; acc.w += v1.w;
        acc.x += v2.x; acc.y += v2.y; acc.z += v2.z; acc.w += v2.w;
        acc.x += v3.x; acc.y += v3.y; acc.z += v3.z; acc.w += v3.w;
    }
    for (; j < je; j++) {
        int s = g_csr[j];
        float4 v = *(const float4*)(x + (size_t)s * F + t * 4);
        acc.x += v.x; acc.y += v.y; acc.z += v.z; acc.w += v.w;
    }
    *(float4*)(g_h + (size_t)node * F + t * 4) = acc;
}

// ---------------------------------------------------------------------------
// g_x = relu( relu(g_h @ W1 + b1) @ W2 + b2 )
// 128-row tile per block, 512 threads as 16x32, 4x4 register microtile.
// ---------------------------------------------------------------------------
__global__ __launch_bounds__(512) void mlp_kernel(
        const float* __restrict__ W1, const float* __restrict__ b1,
        const float* __restrict__ W2, const float* __restrict__ b2) {
    __shared__ float Hs[128][64];
    __shared__ float Ws[64][64];

    int tid = threadIdx.x;
    int tx = tid & 15;
    int ty = tid >> 4;
    int row0 = blockIdx.x * 128;

    for (int i = tid; i < 128 * 16; i += 512) {
        int r = i >> 4;
        int c = (i & 15) << 2;
        float4 v = make_float4(0.f, 0.f, 0.f, 0.f);
        if (row0 + r < N_NODES) v = *(const float4*)(g_h + (size_t)(row0 + r) * F + c);
        *(float4*)&Hs[r][c] = v;
    }
    for (int i = tid; i < 1024; i += 512)
        ((float4*)&Ws[0][0])[i] = ((const float4*)W1)[i];
    float4 bias = *(const float4*)&b1[tx * 4];
    __syncthreads();

    float acc[4][4];
#pragma unroll
    for (int i = 0; i < 4; i++) {
        acc[i][0] = bias.x; acc[i][1] = bias.y; acc[i][2] = bias.z; acc[i][3] = bias.w;
    }

#pragma unroll 8
    for (int k = 0; k < 64; k++) {
        float a0 = Hs[ty * 4 + 0][k];
        float a1 = Hs[ty * 4 + 1][k];
        float a2 = Hs[ty * 4 + 2][k];
        float a3 = Hs[ty * 4 + 3][k];
        float4 b = *(float4*)&Ws[k][tx * 4];
        acc[0][0] += a0 * b.x; acc[0][1] += a0 * b.y; acc[0][2] += a0 * b.z; acc[0][3] += a0 * b.w;
        acc[1][0] += a1 * b.x; acc[1][1] += a1 * b.y; acc[1][2] += a1 * b.z; acc[1][3] += a1 * b.w;
        acc[2][0] += a2 * b.x; acc[2][1] += a2 * b.y; acc[2][2] += a2 * b.z; acc[2][3] += a2 * b.w;
        acc[3][0] += a3 * b.x; acc[3][1] += a3 * b.y; acc[3][2] += a3 * b.z; acc[3][3] += a3 * b.w;
    }
    __syncthreads();

#pragma unroll
    for (int i = 0; i < 4; i++)
#pragma unroll
        for (int j = 0; j < 4; j++)
            Hs[ty * 4 + i][tx * 4 + j] = fmaxf(acc[i][j], 0.f);
    for (int i = tid; i < 1024; i += 512)
        ((float4*)&Ws[0][0])[i] = ((const float4*)W2)[i];
    bias = *(const float4*)&b2[tx * 4];
    __syncthreads();

#pragma unroll
    for (int i = 0; i < 4; i++) {
        acc[i][0] = bias.x; acc[i][1] = bias.y; acc[i][2] = bias.z; acc[i][3] = bias.w;
    }

#pragma unroll 8
    for (int k = 0; k < 64; k++) {
        float a0 = Hs[ty * 4 + 0][k];
        float a1 = Hs[ty * 4 + 1][k];
        float a2 = Hs[ty * 4 + 2][k];
        float a3 = Hs[ty * 4 + 3][k];
        float4 b = *(float4*)&Ws[k][tx * 4];
        acc[0][0] += a0 * b.x; acc[0][1] += a0 * b.y; acc[0][2] += a0 * b.z; acc[0][3] += a0 * b.w;
        acc[1][0] += a1 * b.x; acc[1][1] += a1 * b.y; acc[1][2] += a1 * b.z; acc[1][3] += a1 * b.w;
        acc[2][0] += a2 * b.x; acc[2][1] += a2 * b.y; acc[2][2] += a2 * b.z; acc[2][3] += a2 * b.w;
        acc[3][0] += a3 * b.x; acc[3][1] += a3 * b.y; acc[3][2] += a3 * b.z; acc[3][3] += a3 * b.w;
    }

#pragma unroll
    for (int i = 0; i < 4; i++) {
        int r = row0 + ty * 4 + i;
        if (r < N_NODES) {
            float4 o;
            o.x = fmaxf(acc[i][0], 0.f); o.y = fmaxf(acc[i][1], 0.f);
            o.z = fmaxf(acc[i][2], 0.f); o.w = fmaxf(acc[i][3], 0.f);
            *(float4*)(g_x + (size_t)r * F + tx * 4) = o;
        }
    }
}

// ---------------------------------------------------------------------------
// out = g_x @ W_lin + b_lin   (64 -> 10)
// ---------------------------------------------------------------------------
__global__ void lin_kernel(const float* __restrict__ W, const float* __restrict__ b,
                           float* __restrict__ out) {
    __shared__ float Xs[128][65];
    __shared__ float Ws[64 * NCLS];
    __shared__ float bs[NCLS];

    int tid = threadIdx.x;
    int row0 = blockIdx.x * 128;

    for (int i = tid; i < 128 * 16; i += 128) {
        int r = i >> 4;
        int c = (i & 15) << 2;
        float4 v = make_float4(0.f, 0.f, 0.f, 0.f);
        if (row0 + r < N_NODES) v = *(const float4*)(g_x + (size_t)(row0 + r) * F + c);
        Xs[r][c] = v.x; Xs[r][c + 1] = v.y; Xs[r][c + 2] = v.z; Xs[r][c + 3] = v.w;
    }
    for (int i = tid; i < 64 * NCLS; i += 128) Ws[i] = W[i];
    if (tid < NCLS) bs[tid] = b[tid];
    __syncthreads();

    int row = row0 + tid;
    float acc[NCLS];
#pragma unroll
    for (int c = 0; c < NCLS; c++) acc[c] = bs[c];
#pragma unroll 8
    for (int k = 0; k < 64; k++) {
        float xv = Xs[tid][k];
#pragma unroll
        for (int c = 0; c < NCLS; c++) acc[c] += xv * Ws[k * NCLS + c];
    }
    if (row < N_NODES) {
#pragma unroll
        for (int c = 0; c < NCLS; c++) out[(size_t)row * NCLS + c] = acc[c];
    }
}

// ---------------------------------------------------------------------------
// Launch: kernel launches ONLY.
// ---------------------------------------------------------------------------
extern "C" void kernel_launch(void* const* d_in, const int* in_sizes, int n_in,
                              void* d_out, int out_size) {
    const float* feat      = (const float*)d_in[0];
    const int*   edges_raw = (const int*)d_in[1];

    const float* W1[3] = { (const float*)d_in[2],  (const float*)d_in[6],  (const float*)d_in[10] };
    const float* b1[3] = { (const float*)d_in[3],  (const float*)d_in[7],  (const float*)d_in[11] };
    const float* W2[3] = { (const float*)d_in[4],  (const float*)d_in[8],  (const float*)d_in[12] };
    const float* b2[3] = { (const float*)d_in[5],  (const float*)d_in[9],  (const float*)d_in[13] };
    const float* Wl = (const float*)d_in[14];
    const float* bl = (const float*)d_in[15];
    float* out = (float*)d_out;

    dim3 edge4_grid((N_EDGES / 4 + 255) / 256);
    dim3 agg_grid((N_NODES + 15) / 16);
    dim3 mlp_grid((N_NODES + 127) / 128);
    dim3 lin_grid((N_NODES + 127) / 128);

    init_kernel<<<NODE_BLOCKS + 1, 256>>>(edges_raw);
    hist_kernel<<<edge4_grid, 256>>>(edges_raw);
    scan_local_kernel<<<SCAN_BLOCKS, SCAN_CHUNK>>>();
    scan_spine_kernel<<<1, 128>>>();
    scan_add_kernel<<<SCAN_BLOCKS, SCAN_CHUNK>>>();
    csr_scatter_kernel<<<edge4_grid, 256>>>(edges_raw);

    for (int l = 0; l < 3; l++) {
        agg_kernel<<<agg_grid, 256>>>(feat, l == 0 ? 1 : 0);
        mlp_kernel<<<mlp_grid, 512>>>(W1[l], b1[l], W2[l], b2[l]);
    }
    lin_kernel<<<lin_grid, 128>>>(Wl, bl, out);
}